// round 10
// baseline (speedup 1.0000x reference)
#include <cuda_runtime.h>
#include <cuda_fp16.h>
#include <cstdint>

// Problem constants
#define B_  8
#define C_  128
#define H_  256
#define W_  256
#define KB_ 4
#define OC_ 128

// Scratch (static device arrays; no allocation)
__device__ float g_pooled[B_ * C_];
__device__ float g_dynk[B_ * C_ * 9];
// pw_w rounded to fp16, packed in m16n8k16 B-fragment order:
// [ci(8)][nt(16)][lane(32)] x uint2 {b0, b1}
__device__ uint2 g_pwf16[8 * 16 * 32];

// ---------------------------------------------------------------------------
// helpers
// ---------------------------------------------------------------------------
__device__ __forceinline__ uint32_t smem_u32(const void* p) {
    uint32_t a;
    asm("{ .reg .u64 t; cvta.to.shared.u64 t, %1; cvt.u32.u64 %0, t; }"
        : "=r"(a) : "l"(p));
    return a;
}
__device__ __forceinline__ void mma_f16(float* d, const uint32_t* a,
                                        uint32_t b0, uint32_t b1) {
    asm volatile(
        "mma.sync.aligned.m16n8k16.row.col.f32.f16.f16.f32 "
        "{%0,%1,%2,%3}, {%4,%5,%6,%7}, {%8,%9}, {%0,%1,%2,%3};"
        : "+f"(d[0]), "+f"(d[1]), "+f"(d[2]), "+f"(d[3])
        : "r"(a[0]), "r"(a[1]), "r"(a[2]), "r"(a[3]), "r"(b0), "r"(b1));
}
// split float into fp16 hi (low 16 bits) + fp16 residual (high 16 bits)
__device__ __forceinline__ uint32_t split_f16_pair(float v) {
    __half h = __float2half_rn(v);
    __half l = __float2half_rn(v - __half2float(h));
    return (uint32_t)__half_as_ushort(h)
         | ((uint32_t)__half_as_ushort(l) << 16);
}

// ---------------------------------------------------------------------------
// Kernel 1: global average pool
// ---------------------------------------------------------------------------
__global__ void pool_kernel(const float* __restrict__ x) {
    const int plane = blockIdx.x;
    const int t = threadIdx.x;
    const float4* p = reinterpret_cast<const float4*>(x + (size_t)plane * (H_ * W_));
    float s = 0.f;
#pragma unroll 8
    for (int it = 0; it < 64; it++) {
        float4 v = p[it * 256 + t];
        s += (v.x + v.y) + (v.z + v.w);
    }
    __shared__ float red[256];
    red[t] = s;
    __syncthreads();
    for (int st = 128; st > 0; st >>= 1) {
        if (t < st) red[t] += red[t + st];
        __syncthreads();
    }
    if (t == 0) g_pooled[plane] = red[0] * (1.f / (H_ * W_));
}

// ---------------------------------------------------------------------------
// Kernel 2: attention -> softmax -> dynamic depthwise kernel per (b,c)
// ---------------------------------------------------------------------------
__global__ void attn_kernel(const float* __restrict__ kernel_bank,
                            const float* __restrict__ attn_w,
                            const float* __restrict__ attn_b) {
    const int b = blockIdx.x;
    const int c = threadIdx.x;               // 128 threads
    __shared__ float red[128];
    __shared__ float logit[KB_];
    __shared__ float attn[KB_];

    float p = g_pooled[b * C_ + c];
    for (int k = 0; k < KB_; k++) {
        red[c] = p * attn_w[k * C_ + c];
        __syncthreads();
        for (int st = 64; st > 0; st >>= 1) {
            if (c < st) red[c] += red[c + st];
            __syncthreads();
        }
        if (c == 0) logit[k] = red[0] + attn_b[k];
        __syncthreads();
    }
    if (c == 0) {
        float mx = logit[0];
        for (int k = 1; k < KB_; k++) mx = fmaxf(mx, logit[k]);
        float s = 0.f;
        for (int k = 0; k < KB_; k++) { attn[k] = expf(logit[k] - mx); s += attn[k]; }
        float inv = 1.f / s;
        for (int k = 0; k < KB_; k++) attn[k] *= inv;
    }
    __syncthreads();
    float a0 = attn[0], a1 = attn[1], a2 = attn[2], a3 = attn[3];
#pragma unroll
    for (int ij = 0; ij < 9; ij++) {
        float s = a0 * kernel_bank[(0 * C_ + c) * 9 + ij]
                + a1 * kernel_bank[(1 * C_ + c) * 9 + ij]
                + a2 * kernel_bank[(2 * C_ + c) * 9 + ij]
                + a3 * kernel_bank[(3 * C_ + c) * 9 + ij];
        g_dynk[(b * C_ + c) * 9 + ij] = s;
    }
}

// ---------------------------------------------------------------------------
// Kernel 2b: round pw_w to fp16, packed in B-fragment order.
// ---------------------------------------------------------------------------
__global__ void split_pw_fp16(const float* __restrict__ pw_w) {
    int idx = blockIdx.x * 256 + threadIdx.x;   // (ci, nt, lane)
    if (idx >= 4096) return;
    int lane = idx & 31;
    int nt   = (idx >> 5) & 15;
    int ci   = idx >> 9;
    int g = lane >> 2, tig = lane & 3;
    int o  = nt * 8 + g;
    int k0 = ci * 16 + 2 * tig;

    uint32_t b0 = (uint32_t)__half_as_ushort(__float2half_rn(pw_w[o * C_ + k0]))
                | ((uint32_t)__half_as_ushort(__float2half_rn(pw_w[o * C_ + k0 + 1])) << 16);
    uint32_t b1 = (uint32_t)__half_as_ushort(__float2half_rn(pw_w[o * C_ + k0 + 8]))
                | ((uint32_t)__half_as_ushort(__float2half_rn(pw_w[o * C_ + k0 + 9])) << 16);
    g_pwf16[idx] = make_uint2(b0, b1);
}

// ---------------------------------------------------------------------------
// Fused dw 3x3 + mma.sync fp16 GEMM (2-term fp16 A-split, fp16 B).
// Grid (W/128=2, H=256, B*2=16: z = b*2 + nh), 256 threads, 3 CTAs/SM.
// CTA tile: M=128 pixels (one row strip) x N=64 ocs (half, selected by nh).
// 8 warps: 4 m-warps (m32) x 2 n-warps (n32); acc 32 floats/thread.
// dw on all warps: thread (kch = t&15, mg = t>>4) -> 8 px.
// B fragments via direct __ldg (uint2 per nt).
// Smem (floats):
//   As[2] : buf stride 2080 (hi 1024 @+0, lo 1024 @+1040)
//   xs[2] : 16ch x 3rows x 140  (ch stride 420 fl = 105 x 16B, odd -> CF)
//   dk    : 1152
// Total 18752 floats = 75008 B -> 3 CTAs/SM.
// ---------------------------------------------------------------------------
#define XS_ROW   140
#define XS_FLTS  (16 * 3 * XS_ROW)          // 6720 per buffer
#define AS_F     0
#define AS_LO_D  1040
#define AS_STRIDE 2080
#define XS_F     4160
#define DK_F     (XS_F + 2 * XS_FLTS)       // 17600
#define SMEM_FLOATS (DK_F + 1152)           // 18752 -> 75008 B

__device__ __forceinline__ void stage_xs(const float* __restrict__ x,
                                         int b, int c0, int h, int w0,
                                         float* xf, int t) {
    // interior: 16 ch x 3 rows x 32 float4 = 1536 f4, 6 per thread
#pragma unroll
    for (int i = 0; i < 6; i++) {
        int idx = t + i * 256;
        int c   = idx / 96;
        int rem = idx - c * 96;
        int r   = rem >> 5;
        int q   = rem & 31;
        int hh  = h + r - 1;
        float* dst = xf + (c * 3 + r) * XS_ROW + 4 + q * 4;
        if ((unsigned)hh < (unsigned)H_) {
            const float* src = x + (((size_t)(b * C_ + c0 + c)) * H_ + hh) * W_ + w0 + q * 4;
            asm volatile("cp.async.cg.shared.global [%0], [%1], 16;"
                         :: "r"(smem_u32(dst)), "l"(src));
        } else {
            *reinterpret_cast<float4*>(dst) = make_float4(0.f, 0.f, 0.f, 0.f);
        }
    }
    // halo columns: 16 ch x 3 rows x 2 sides = 96 scalars
    if (t < 96) {
        int c    = t / 6;
        int rem  = t - c * 6;
        int r    = rem >> 1;
        int side = rem & 1;
        int hh   = h + r - 1;
        int ww   = side ? (w0 + 128) : (w0 - 1);
        int col  = side ? 132 : 3;
        float* dst = xf + (c * 3 + r) * XS_ROW + col;
        if ((unsigned)hh < (unsigned)H_ && (unsigned)ww < (unsigned)W_) {
            const float* src = x + (((size_t)(b * C_ + c0 + c)) * H_ + hh) * W_ + ww;
            asm volatile("cp.async.ca.shared.global [%0], [%1], 4;"
                         :: "r"(smem_u32(dst)), "l"(src));
        } else {
            *dst = 0.f;
        }
    }
}

// depthwise for chunk cj: 8 pixels per thread, one output row
__device__ __forceinline__ void dw_chunk(float* smem, int cj, int kch, int mg,
                                         int wb, int a_lo_sel, uint32_t psel) {
    const float* dk   = smem + DK_F;
    const float* dkc  = dk + (cj * 16 + kch) * 9;
    const float* rowb = smem + XS_F + (cj & 1) * XS_FLTS + kch * 3 * XS_ROW + mg * 8;
    float sv[8];
#pragma unroll
    for (int j = 0; j < 8; j++) sv[j] = 0.f;
#pragma unroll
    for (int r = 0; r < 3; r++) {
        const float* rp = rowb + r * XS_ROW;
        float4 q0 = *reinterpret_cast<const float4*>(rp);
        float4 q1 = *reinterpret_cast<const float4*>(rp + 4);
        float4 q2 = *reinterpret_cast<const float4*>(rp + 8);
        float4 q3 = *reinterpret_cast<const float4*>(rp + 12);
        float v[16] = {q0.x, q0.y, q0.z, q0.w, q1.x, q1.y, q1.z, q1.w,
                       q2.x, q2.y, q2.z, q2.w, q3.x, q3.y, q3.z, q3.w};
        float k0 = dkc[r * 3 + 0], k1 = dkc[r * 3 + 1], k2 = dkc[r * 3 + 2];
#pragma unroll
        for (int j = 0; j < 8; j++) {
            sv[j] = fmaf(k0, v[j + 3], sv[j]);
            sv[j] = fmaf(k1, v[j + 4], sv[j]);
            sv[j] = fmaf(k2, v[j + 5], sv[j]);
        }
    }
    float* abase = smem + AS_F + (cj & 1) * AS_STRIDE + a_lo_sel;
#pragma unroll
    for (int j = 0; j < 8; j++) {
        uint32_t own = split_f16_pair(sv[j]);
        uint32_t partner = __shfl_xor_sync(0xffffffffu, own, 1);
        abase[wb + j * 16] = __uint_as_float(__byte_perm(own, partner, psel));
    }
}

__global__ __launch_bounds__(256, 3)
void fused_kernel(const float* __restrict__ x,
                  const float* __restrict__ pw_b,
                  float* __restrict__ out) {
    extern __shared__ float smem[];
    float* dk = smem + DK_F;

    const int t    = threadIdx.x;
    const int wid  = t >> 5;
    const int lane = t & 31;
    const int w0   = blockIdx.x * 128;
    const int h    = blockIdx.y;
    const int bb   = blockIdx.z >> 1;
    const int nh   = blockIdx.z & 1;         // oc half

    // dw mapping
    const int kch = t & 15;
    const int mg  = t >> 4;                   // 0..15
    const int wb = (mg >> 1) * 128 + ((kch >> 1) & 3) * 4
                 + (kch >> 3) * 2 + (mg & 1);
    const int a_lo_sel = (kch & 1) ? AS_LO_D : 0;
    const uint32_t psel = (kch & 1) ? 0x3276u : 0x5410u;

    // GEMM warp tiling: 4 m-warps x 2 n-warps, warp tile m32 x n32
    const int wm = wid & 3;
    const int wn = wid >> 2;
    // B fragment source: nt = nh*8 + wn*4 + ntl
    const uint2* bsrc = g_pwf16 + (nh * 8 + wn * 4) * 32 + lane;

    // prologue
    stage_xs(x, bb, 0, h, w0, smem + XS_F, t);
    asm volatile("cp.async.commit_group;" ::: "memory");
    for (int i = t; i < C_ * 9; i += 256)
        dk[i] = g_dynk[bb * C_ * 9 + i];

    float acc[2][4][4];
#pragma unroll
    for (int i = 0; i < 2; i++)
#pragma unroll
        for (int j = 0; j < 4; j++)
#pragma unroll
            for (int k = 0; k < 4; k++) acc[i][j][k] = 0.f;

    asm volatile("cp.async.wait_group 0;" ::: "memory");
    __syncthreads();
    stage_xs(x, bb, 16, h, w0, smem + XS_F + XS_FLTS, t);
    asm volatile("cp.async.commit_group;" ::: "memory");

    dw_chunk(smem, 0, kch, mg, wb, a_lo_sel, psel);

#pragma unroll 1
    for (int ci = 0; ci < 8; ci++) {
        if (ci < 7)
            asm volatile("cp.async.wait_group 0;" ::: "memory");
        __syncthreads();   // dw(ci) visible; GEMM(ci-1) done with As[(ci+1)&1]

        // B fragments for GEMM(ci): direct LDG, latency covered by dw below
        uint2 bfrag[4];
#pragma unroll
        for (int ntl = 0; ntl < 4; ntl++)
            bfrag[ntl] = __ldg(bsrc + ci * 512 + ntl * 32);

        if (ci < 6) {
            stage_xs(x, bb, (ci + 2) * 16, h, w0, smem + XS_F + (ci & 1) * XS_FLTS, t);
            asm volatile("cp.async.commit_group;" ::: "memory");
        }

        // dw(ci+1) overlaps GEMM(ci) across warps
        if (ci < 7)
            dw_chunk(smem, ci + 1, kch, mg, wb, a_lo_sel, psel);

        // --- GEMM(ci): one k16 step, 2-term fp16 split ---
        {
            const float* asb = smem + AS_F + (ci & 1) * AS_STRIDE;
            uint4 ah[2], al[2];
#pragma unroll
            for (int mA = 0; mA < 2; mA++) {
                int fi = ((wm * 2 + mA) * 32 + lane) * 4;
                ah[mA] = *reinterpret_cast<const uint4*>(asb + fi);
                al[mA] = *reinterpret_cast<const uint4*>(asb + AS_LO_D + fi);
            }
#pragma unroll
            for (int ntl = 0; ntl < 4; ntl++) {
                uint2 bv = bfrag[ntl];
#pragma unroll
                for (int mA = 0; mA < 2; mA++) {
                    float* a4 = acc[mA][ntl];
                    mma_f16(a4, reinterpret_cast<uint32_t*>(&ah[mA]), bv.x, bv.y);
                    mma_f16(a4, reinterpret_cast<uint32_t*>(&al[mA]), bv.x, bv.y);
                }
            }
        }
    }

    // --- epilogue: D fragment scatter + bias ---
    const int g   = lane >> 2;
    const int tig = lane & 3;
#pragma unroll
    for (int mA = 0; mA < 2; mA++) {
        int mbase = wm * 32 + mA * 16;
#pragma unroll
        for (int ntl = 0; ntl < 4; ntl++) {
            int o = nh * 64 + wn * 32 + ntl * 8 + 2 * tig;
            float b0v = __ldg(pw_b + o);
            float b1v = __ldg(pw_b + o + 1);
            size_t r0 = (((size_t)(bb * OC_ + o)) * H_ + h) * W_ + w0 + mbase;
            size_t r1 = r0 + (size_t)H_ * W_;
            const float* a4 = acc[mA][ntl];
            out[r0 + g]     = a4[0] + b0v;
            out[r1 + g]     = a4[1] + b1v;
            out[r0 + g + 8] = a4[2] + b0v;
            out[r1 + g + 8] = a4[3] + b1v;
        }
    }
}

// ---------------------------------------------------------------------------
extern "C" void kernel_launch(void* const* d_in, const int* in_sizes, int n_in,
                              void* d_out, int out_size) {
    const float* x           = (const float*)d_in[0];
    const float* kernel_bank = (const float*)d_in[1];
    const float* attn_w      = (const float*)d_in[2];
    const float* attn_b      = (const float*)d_in[3];
    const float* pw_w        = (const float*)d_in[4];
    const float* pw_b        = (const float*)d_in[5];
    float* out               = (float*)d_out;

    static int smem_set = 0;
    if (!smem_set) {
        cudaFuncSetAttribute(fused_kernel,
                             cudaFuncAttributeMaxDynamicSharedMemorySize,
                             SMEM_FLOATS * 4);
        smem_set = 1;
    }

    pool_kernel<<<B_ * C_, 256>>>(x);
    attn_kernel<<<B_, 128>>>(kernel_bank, attn_w, attn_b);
    split_pw_fp16<<<16, 256>>>(pw_w);
    fused_kernel<<<dim3(W_ / 128, H_, B_ * 2), 256, SMEM_FLOATS * 4>>>(x, pw_b, out);
}

// round 11
// speedup vs baseline: 1.2807x; 1.2807x over previous
#include <cuda_runtime.h>
#include <cuda_fp16.h>
#include <cstdint>

// Problem constants
#define B_  8
#define C_  128
#define H_  256
#define W_  256
#define KB_ 4
#define OC_ 128

// Scratch (static device arrays; no allocation)
__device__ float g_pooled[B_ * C_];
__device__ float g_dynk[B_ * C_ * 9];
// pw_w rounded to fp16, packed in m16n8k16 B-fragment order:
// [ci(8)][nt(16)][lane(32)] x uint2 {b0, b1}
__device__ uint2 g_pwf16[8 * 16 * 32];

// ---------------------------------------------------------------------------
// helpers
// ---------------------------------------------------------------------------
__device__ __forceinline__ uint32_t smem_u32(const void* p) {
    uint32_t a;
    asm("{ .reg .u64 t; cvta.to.shared.u64 t, %1; cvt.u32.u64 %0, t; }"
        : "=r"(a) : "l"(p));
    return a;
}
__device__ __forceinline__ void mma_f16(float* d, const uint32_t* a,
                                        uint32_t b0, uint32_t b1) {
    asm volatile(
        "mma.sync.aligned.m16n8k16.row.col.f32.f16.f16.f32 "
        "{%0,%1,%2,%3}, {%4,%5,%6,%7}, {%8,%9}, {%0,%1,%2,%3};"
        : "+f"(d[0]), "+f"(d[1]), "+f"(d[2]), "+f"(d[3])
        : "r"(a[0]), "r"(a[1]), "r"(a[2]), "r"(a[3]), "r"(b0), "r"(b1));
}
// split float into fp16 hi (low 16 bits) + fp16 residual (high 16 bits)
__device__ __forceinline__ uint32_t split_f16_pair(float v) {
    __half h = __float2half_rn(v);
    __half l = __float2half_rn(v - __half2float(h));
    return (uint32_t)__half_as_ushort(h)
         | ((uint32_t)__half_as_ushort(l) << 16);
}

// ---------------------------------------------------------------------------
// Kernel 1: global average pool
// ---------------------------------------------------------------------------
__global__ void pool_kernel(const float* __restrict__ x) {
    const int plane = blockIdx.x;
    const int t = threadIdx.x;
    const float4* p = reinterpret_cast<const float4*>(x + (size_t)plane * (H_ * W_));
    float s = 0.f;
#pragma unroll 8
    for (int it = 0; it < 64; it++) {
        float4 v = p[it * 256 + t];
        s += (v.x + v.y) + (v.z + v.w);
    }
    __shared__ float red[256];
    red[t] = s;
    __syncthreads();
    for (int st = 128; st > 0; st >>= 1) {
        if (t < st) red[t] += red[t + st];
        __syncthreads();
    }
    if (t == 0) g_pooled[plane] = red[0] * (1.f / (H_ * W_));
}

// ---------------------------------------------------------------------------
// Kernel 2: attention -> softmax -> dynamic depthwise kernel per (b,c)
// ---------------------------------------------------------------------------
__global__ void attn_kernel(const float* __restrict__ kernel_bank,
                            const float* __restrict__ attn_w,
                            const float* __restrict__ attn_b) {
    const int b = blockIdx.x;
    const int c = threadIdx.x;               // 128 threads
    __shared__ float red[128];
    __shared__ float logit[KB_];
    __shared__ float attn[KB_];

    float p = g_pooled[b * C_ + c];
    for (int k = 0; k < KB_; k++) {
        red[c] = p * attn_w[k * C_ + c];
        __syncthreads();
        for (int st = 64; st > 0; st >>= 1) {
            if (c < st) red[c] += red[c + st];
            __syncthreads();
        }
        if (c == 0) logit[k] = red[0] + attn_b[k];
        __syncthreads();
    }
    if (c == 0) {
        float mx = logit[0];
        for (int k = 1; k < KB_; k++) mx = fmaxf(mx, logit[k]);
        float s = 0.f;
        for (int k = 0; k < KB_; k++) { attn[k] = expf(logit[k] - mx); s += attn[k]; }
        float inv = 1.f / s;
        for (int k = 0; k < KB_; k++) attn[k] *= inv;
    }
    __syncthreads();
    float a0 = attn[0], a1 = attn[1], a2 = attn[2], a3 = attn[3];
#pragma unroll
    for (int ij = 0; ij < 9; ij++) {
        float s = a0 * kernel_bank[(0 * C_ + c) * 9 + ij]
                + a1 * kernel_bank[(1 * C_ + c) * 9 + ij]
                + a2 * kernel_bank[(2 * C_ + c) * 9 + ij]
                + a3 * kernel_bank[(3 * C_ + c) * 9 + ij];
        g_dynk[(b * C_ + c) * 9 + ij] = s;
    }
}

// ---------------------------------------------------------------------------
// Kernel 2b: round pw_w to fp16, packed in B-fragment order.
// ---------------------------------------------------------------------------
__global__ void split_pw_fp16(const float* __restrict__ pw_w) {
    int idx = blockIdx.x * 256 + threadIdx.x;   // (ci, nt, lane)
    if (idx >= 4096) return;
    int lane = idx & 31;
    int nt   = (idx >> 5) & 15;
    int ci   = idx >> 9;
    int g = lane >> 2, tig = lane & 3;
    int o  = nt * 8 + g;
    int k0 = ci * 16 + 2 * tig;

    uint32_t b0 = (uint32_t)__half_as_ushort(__float2half_rn(pw_w[o * C_ + k0]))
                | ((uint32_t)__half_as_ushort(__float2half_rn(pw_w[o * C_ + k0 + 1])) << 16);
    uint32_t b1 = (uint32_t)__half_as_ushort(__float2half_rn(pw_w[o * C_ + k0 + 8]))
                | ((uint32_t)__half_as_ushort(__float2half_rn(pw_w[o * C_ + k0 + 9])) << 16);
    g_pwf16[idx] = make_uint2(b0, b1);
}

// ---------------------------------------------------------------------------
// Fused dw 3x3 + mma.sync fp16 GEMM (2-term fp16 A-split, fp16 B).
// Grid (W/64=4, H=256, B=8), 256 threads, 3 CTAs/SM.
// CTA tile: M=64 pixels x N=128 ocs (no work duplication).
// 8 warps: 2 m-warps (m32) x 4 n-warps (n32); acc 32 floats/thread.
// dw: thread (kch = t&15, mg = t>>4) -> 4 px of one row.
// B fragments via direct __ldg.
// Smem (floats):
//   As[2] : buf stride 1056 (hi 512 @+0, lo 512 @+528)
//   xs[2] : 16 ch x 3 rows x 72, ch stride 220 fl (55 16B-units, odd -> CF)
//   dk    : 1152
// Total 10304 floats = 41216 B -> 3 CTAs/SM (regs bind).
// ---------------------------------------------------------------------------
#define XS_ROW   72
#define XS_CH    220
#define XS_FLTS  (16 * XS_CH)               // 3520 per buffer
#define AS_F     0
#define AS_LO_D  528
#define AS_STRIDE 1056
#define XS_F     (2 * AS_STRIDE)            // 2112
#define DK_F     (XS_F + 2 * XS_FLTS)       // 9152
#define SMEM_FLOATS (DK_F + 1152)           // 10304 -> 41216 B

__device__ __forceinline__ void stage_xs(const float* __restrict__ x,
                                         int b, int c0, int h, int w0,
                                         float* xf, int t) {
    // interior: 16 ch x 3 rows x 16 float4 = 768 f4, 3 per thread
#pragma unroll
    for (int i = 0; i < 3; i++) {
        int idx = t + i * 256;
        int c   = idx / 48;
        int rem = idx - c * 48;
        int r   = rem >> 4;
        int q   = rem & 15;
        int hh  = h + r - 1;
        float* dst = xf + c * XS_CH + r * XS_ROW + 4 + q * 4;
        if ((unsigned)hh < (unsigned)H_) {
            const float* src = x + (((size_t)(b * C_ + c0 + c)) * H_ + hh) * W_ + w0 + q * 4;
            asm volatile("cp.async.cg.shared.global [%0], [%1], 16;"
                         :: "r"(smem_u32(dst)), "l"(src));
        } else {
            *reinterpret_cast<float4*>(dst) = make_float4(0.f, 0.f, 0.f, 0.f);
        }
    }
    // halo columns: 16 ch x 3 rows x 2 sides = 96 scalars
    if (t < 96) {
        int c    = t / 6;
        int rem  = t - c * 6;
        int r    = rem >> 1;
        int side = rem & 1;
        int hh   = h + r - 1;
        int ww   = side ? (w0 + 64) : (w0 - 1);
        int col  = side ? 68 : 3;
        float* dst = xf + c * XS_CH + r * XS_ROW + col;
        if ((unsigned)hh < (unsigned)H_ && (unsigned)ww < (unsigned)W_) {
            const float* src = x + (((size_t)(b * C_ + c0 + c)) * H_ + hh) * W_ + ww;
            asm volatile("cp.async.ca.shared.global [%0], [%1], 4;"
                         :: "r"(smem_u32(dst)), "l"(src));
        } else {
            *dst = 0.f;
        }
    }
}

// depthwise for chunk cj: 4 pixels per thread
__device__ __forceinline__ void dw_chunk(float* smem, int cj, int kch, int mg,
                                         int wb, int a_lo_sel, uint32_t psel) {
    const float* dk   = smem + DK_F;
    const float* dkc  = dk + (cj * 16 + kch) * 9;
    const float* rowb = smem + XS_F + (cj & 1) * XS_FLTS + kch * XS_CH + mg * 4;
    float sv[4];
#pragma unroll
    for (int j = 0; j < 4; j++) sv[j] = 0.f;
#pragma unroll
    for (int r = 0; r < 3; r++) {
        const float* rp = rowb + r * XS_ROW;
        float4 q0 = *reinterpret_cast<const float4*>(rp);
        float4 q1 = *reinterpret_cast<const float4*>(rp + 4);
        float4 q2 = *reinterpret_cast<const float4*>(rp + 8);
        float v[12] = {q0.x, q0.y, q0.z, q0.w, q1.x, q1.y, q1.z, q1.w,
                       q2.x, q2.y, q2.z, q2.w};
        float k0 = dkc[r * 3 + 0], k1 = dkc[r * 3 + 1], k2 = dkc[r * 3 + 2];
#pragma unroll
        for (int j = 0; j < 4; j++) {
            sv[j] = fmaf(k0, v[j + 3], sv[j]);
            sv[j] = fmaf(k1, v[j + 4], sv[j]);
            sv[j] = fmaf(k2, v[j + 5], sv[j]);
        }
    }
    float* abase = smem + AS_F + (cj & 1) * AS_STRIDE + a_lo_sel;
#pragma unroll
    for (int j = 0; j < 4; j++) {
        uint32_t own = split_f16_pair(sv[j]);
        uint32_t partner = __shfl_xor_sync(0xffffffffu, own, 1);
        abase[wb + j * 16] = __uint_as_float(__byte_perm(own, partner, psel));
    }
}

__global__ __launch_bounds__(256, 3)
void fused_kernel(const float* __restrict__ x,
                  const float* __restrict__ pw_b,
                  float* __restrict__ out) {
    extern __shared__ float smem[];
    float* dk = smem + DK_F;

    const int t    = threadIdx.x;
    const int wid  = t >> 5;
    const int lane = t & 31;
    const int w0   = blockIdx.x * 64;
    const int h    = blockIdx.y;
    const int bb   = blockIdx.z;

    // dw mapping: channel kch, 4-px group mg (pixels m = mg*4 + j)
    const int kch = t & 15;
    const int mg  = t >> 4;                   // 0..15
    // A-frag word index for (m = mg*4+j, k = kch): base + j*16
    const int wb = (mg >> 2) * 128 + (mg & 1) * 64 + ((kch >> 1) & 3) * 4
                 + (kch >> 3) * 2 + ((mg >> 1) & 1);
    const int a_lo_sel = (kch & 1) ? AS_LO_D : 0;
    const uint32_t psel = (kch & 1) ? 0x3276u : 0x5410u;

    // GEMM warp tiling: 2 m-warps x 4 n-warps, warp tile m32 x n32
    const int wm = wid & 1;
    const int wn = wid >> 1;
    const uint2* bsrc = g_pwf16 + (wn * 4) * 32 + lane;

    // prologue
    stage_xs(x, bb, 0, h, w0, smem + XS_F, t);
    asm volatile("cp.async.commit_group;" ::: "memory");
    for (int i = t; i < C_ * 9; i += 256)
        dk[i] = g_dynk[bb * C_ * 9 + i];

    float acc[2][4][4];
#pragma unroll
    for (int i = 0; i < 2; i++)
#pragma unroll
        for (int j = 0; j < 4; j++)
#pragma unroll
            for (int k = 0; k < 4; k++) acc[i][j][k] = 0.f;

    asm volatile("cp.async.wait_group 0;" ::: "memory");
    __syncthreads();
    stage_xs(x, bb, 16, h, w0, smem + XS_F + XS_FLTS, t);
    asm volatile("cp.async.commit_group;" ::: "memory");

    dw_chunk(smem, 0, kch, mg, wb, a_lo_sel, psel);

#pragma unroll 1
    for (int ci = 0; ci < 8; ci++) {
        if (ci < 7)
            asm volatile("cp.async.wait_group 0;" ::: "memory");
        __syncthreads();   // dw(ci) visible; GEMM(ci-1) done with As[(ci+1)&1]

        // B fragments for GEMM(ci): direct LDG, latency covered by dw below
        uint2 bfrag[4];
#pragma unroll
        for (int ntl = 0; ntl < 4; ntl++)
            bfrag[ntl] = __ldg(bsrc + ci * 512 + ntl * 32);

        if (ci < 6) {
            stage_xs(x, bb, (ci + 2) * 16, h, w0, smem + XS_F + (ci & 1) * XS_FLTS, t);
            asm volatile("cp.async.commit_group;" ::: "memory");
        }

        // dw(ci+1) overlaps GEMM(ci) across warps
        if (ci < 7)
            dw_chunk(smem, ci + 1, kch, mg, wb, a_lo_sel, psel);

        // --- GEMM(ci): one k16 step, 2-term fp16 split ---
        {
            const float* asb = smem + AS_F + (ci & 1) * AS_STRIDE;
            uint4 ah[2], al[2];
#pragma unroll
            for (int mA = 0; mA < 2; mA++) {
                int fi = ((wm * 2 + mA) * 32 + lane) * 4;
                ah[mA] = *reinterpret_cast<const uint4*>(asb + fi);
                al[mA] = *reinterpret_cast<const uint4*>(asb + AS_LO_D + fi);
            }
#pragma unroll
            for (int ntl = 0; ntl < 4; ntl++) {
                uint2 bv = bfrag[ntl];
#pragma unroll
                for (int mA = 0; mA < 2; mA++) {
                    float* a4 = acc[mA][ntl];
                    mma_f16(a4, reinterpret_cast<uint32_t*>(&ah[mA]), bv.x, bv.y);
                    mma_f16(a4, reinterpret_cast<uint32_t*>(&al[mA]), bv.x, bv.y);
                }
            }
        }
    }

    // --- epilogue: D fragment scatter + bias ---
    const int g   = lane >> 2;
    const int tig = lane & 3;
#pragma unroll
    for (int mA = 0; mA < 2; mA++) {
        int mbase = wm * 32 + mA * 16;
#pragma unroll
        for (int ntl = 0; ntl < 4; ntl++) {
            int o = (wn * 4 + ntl) * 8 + 2 * tig;
            float b0v = __ldg(pw_b + o);
            float b1v = __ldg(pw_b + o + 1);
            size_t r0 = (((size_t)(bb * OC_ + o)) * H_ + h) * W_ + w0 + mbase;
            size_t r1 = r0 + (size_t)H_ * W_;
            const float* a4 = acc[mA][ntl];
            out[r0 + g]     = a4[0] + b0v;
            out[r1 + g]     = a4[1] + b1v;
            out[r0 + g + 8] = a4[2] + b0v;
            out[r1 + g + 8] = a4[3] + b1v;
        }
    }
}

// ---------------------------------------------------------------------------
extern "C" void kernel_launch(void* const* d_in, const int* in_sizes, int n_in,
                              void* d_out, int out_size) {
    const float* x           = (const float*)d_in[0];
    const float* kernel_bank = (const float*)d_in[1];
    const float* attn_w      = (const float*)d_in[2];
    const float* attn_b      = (const float*)d_in[3];
    const float* pw_w        = (const float*)d_in[4];
    const float* pw_b        = (const float*)d_in[5];
    float* out               = (float*)d_out;

    static int smem_set = 0;
    if (!smem_set) {
        cudaFuncSetAttribute(fused_kernel,
                             cudaFuncAttributeMaxDynamicSharedMemorySize,
                             SMEM_FLOATS * 4);
        smem_set = 1;
    }

    pool_kernel<<<B_ * C_, 256>>>(x);
    attn_kernel<<<B_, 128>>>(kernel_bank, attn_w, attn_b);
    split_pw_fp16<<<16, 256>>>(pw_w);
    fused_kernel<<<dim3(W_ / 64, H_, B_), 256, SMEM_FLOATS * 4>>>(x, pw_b, out);
}

// round 12
// speedup vs baseline: 1.3529x; 1.0564x over previous
#include <cuda_runtime.h>
#include <cuda_fp16.h>
#include <cstdint>

// Problem constants
#define B_  8
#define C_  128
#define H_  256
#define W_  256
#define KB_ 4
#define OC_ 128

// Scratch (static device arrays; no allocation)
__device__ float g_pooled[B_ * C_];
__device__ float g_dynk[B_ * C_ * 9];
// pw_w rounded to fp16, packed in m16n8k16 B-fragment order:
// [ci(8)][nt(16)][lane(32)] x uint2 {b0, b1}
__device__ uint2 g_pwf16[8 * 16 * 32];

// ---------------------------------------------------------------------------
// helpers
// ---------------------------------------------------------------------------
__device__ __forceinline__ uint32_t smem_u32(const void* p) {
    uint32_t a;
    asm("{ .reg .u64 t; cvta.to.shared.u64 t, %1; cvt.u32.u64 %0, t; }"
        : "=r"(a) : "l"(p));
    return a;
}
__device__ __forceinline__ void mma_f16(float* d, const uint32_t* a,
                                        uint32_t b0, uint32_t b1) {
    asm volatile(
        "mma.sync.aligned.m16n8k16.row.col.f32.f16.f16.f32 "
        "{%0,%1,%2,%3}, {%4,%5,%6,%7}, {%8,%9}, {%0,%1,%2,%3};"
        : "+f"(d[0]), "+f"(d[1]), "+f"(d[2]), "+f"(d[3])
        : "r"(a[0]), "r"(a[1]), "r"(a[2]), "r"(a[3]), "r"(b0), "r"(b1));
}
// split float into fp16 hi (low 16 bits) + fp16 residual (high 16 bits)
__device__ __forceinline__ uint32_t split_f16_pair(float v) {
    __half h = __float2half_rn(v);
    __half l = __float2half_rn(v - __half2float(h));
    return (uint32_t)__half_as_ushort(h)
         | ((uint32_t)__half_as_ushort(l) << 16);
}

// ---------------------------------------------------------------------------
// Kernel 1: global average pool
// ---------------------------------------------------------------------------
__global__ void pool_kernel(const float* __restrict__ x) {
    const int plane = blockIdx.x;
    const int t = threadIdx.x;
    const float4* p = reinterpret_cast<const float4*>(x + (size_t)plane * (H_ * W_));
    float s = 0.f;
#pragma unroll 8
    for (int it = 0; it < 64; it++) {
        float4 v = p[it * 256 + t];
        s += (v.x + v.y) + (v.z + v.w);
    }
    __shared__ float red[256];
    red[t] = s;
    __syncthreads();
    for (int st = 128; st > 0; st >>= 1) {
        if (t < st) red[t] += red[t + st];
        __syncthreads();
    }
    if (t == 0) g_pooled[plane] = red[0] * (1.f / (H_ * W_));
}

// ---------------------------------------------------------------------------
// Kernel 2: attention -> softmax -> dynamic depthwise kernel per (b,c)
// ---------------------------------------------------------------------------
__global__ void attn_kernel(const float* __restrict__ kernel_bank,
                            const float* __restrict__ attn_w,
                            const float* __restrict__ attn_b) {
    const int b = blockIdx.x;
    const int c = threadIdx.x;               // 128 threads
    __shared__ float red[128];
    __shared__ float logit[KB_];
    __shared__ float attn[KB_];

    float p = g_pooled[b * C_ + c];
    for (int k = 0; k < KB_; k++) {
        red[c] = p * attn_w[k * C_ + c];
        __syncthreads();
        for (int st = 64; st > 0; st >>= 1) {
            if (c < st) red[c] += red[c + st];
            __syncthreads();
        }
        if (c == 0) logit[k] = red[0] + attn_b[k];
        __syncthreads();
    }
    if (c == 0) {
        float mx = logit[0];
        for (int k = 1; k < KB_; k++) mx = fmaxf(mx, logit[k]);
        float s = 0.f;
        for (int k = 0; k < KB_; k++) { attn[k] = expf(logit[k] - mx); s += attn[k]; }
        float inv = 1.f / s;
        for (int k = 0; k < KB_; k++) attn[k] *= inv;
    }
    __syncthreads();
    float a0 = attn[0], a1 = attn[1], a2 = attn[2], a3 = attn[3];
#pragma unroll
    for (int ij = 0; ij < 9; ij++) {
        float s = a0 * kernel_bank[(0 * C_ + c) * 9 + ij]
                + a1 * kernel_bank[(1 * C_ + c) * 9 + ij]
                + a2 * kernel_bank[(2 * C_ + c) * 9 + ij]
                + a3 * kernel_bank[(3 * C_ + c) * 9 + ij];
        g_dynk[(b * C_ + c) * 9 + ij] = s;
    }
}

// ---------------------------------------------------------------------------
// Kernel 2b: round pw_w to fp16, packed in B-fragment order.
// ---------------------------------------------------------------------------
__global__ void split_pw_fp16(const float* __restrict__ pw_w) {
    int idx = blockIdx.x * 256 + threadIdx.x;   // (ci, nt, lane)
    if (idx >= 4096) return;
    int lane = idx & 31;
    int nt   = (idx >> 5) & 15;
    int ci   = idx >> 9;
    int g = lane >> 2, tig = lane & 3;
    int o  = nt * 8 + g;
    int k0 = ci * 16 + 2 * tig;

    uint32_t b0 = (uint32_t)__half_as_ushort(__float2half_rn(pw_w[o * C_ + k0]))
                | ((uint32_t)__half_as_ushort(__float2half_rn(pw_w[o * C_ + k0 + 1])) << 16);
    uint32_t b1 = (uint32_t)__half_as_ushort(__float2half_rn(pw_w[o * C_ + k0 + 8]))
                | ((uint32_t)__half_as_ushort(__float2half_rn(pw_w[o * C_ + k0 + 9])) << 16);
    g_pwf16[idx] = make_uint2(b0, b1);
}

// ---------------------------------------------------------------------------
// Fused dw 3x3 + mma.sync fp16 GEMM (2-term fp16 A-split, fp16 B).
// Grid (W/32=8, H/2=128, B=8), 256 threads, 3 CTAs/SM.
// CTA tile: M=64 = 32 px x 2 output rows, N=128 ocs.
// Stages 4 x-rows per 2 output rows (row amortization).
// dw: thread (kch = t&15, mg = t>>4): row = mg>>3, pxg = mg&7 -> 4 px.
//     Loads per row: 2x LDS.128 + 1x LDS.32 (exactly the 9 floats needed).
// 8 warps GEMM: 2 m-warps (m32) x 4 n-warps (n32); acc 32 floats/thread.
// B fragments via direct __ldg.
// Smem (floats):
//   As[2] : buf stride 1056 (hi 512 @+0, lo 512 @+528)
//   xs[2] : 16 ch x 4 rows x 40, ch stride 164 fl (41 16B-units, odd -> CF)
//   dk    : 1152
// Total 8512 floats = 34 KB -> 3 CTAs/SM (regs bind).
// ---------------------------------------------------------------------------
#define XS_ROW   40
#define XS_CH    164
#define XS_FLTS  (16 * XS_CH)               // 2624 per buffer
#define AS_F     0
#define AS_LO_D  528
#define AS_STRIDE 1056
#define XS_F     (2 * AS_STRIDE)            // 2112
#define DK_F     (XS_F + 2 * XS_FLTS)       // 7360
#define SMEM_FLOATS (DK_F + 1152)           // 8512 -> 34048 B

__device__ __forceinline__ void stage_xs(const float* __restrict__ x,
                                         int b, int c0, int h0, int w0,
                                         float* xf, int t) {
    // interior: 16 ch x 4 rows x 8 float4 = 512 f4, 2 per thread
#pragma unroll
    for (int i = 0; i < 2; i++) {
        int idx = t + i * 256;
        int c   = idx >> 5;
        int rem = idx & 31;
        int r   = rem >> 3;
        int q   = rem & 7;
        int hh  = h0 + r - 1;
        float* dst = xf + c * XS_CH + r * XS_ROW + 4 + q * 4;
        if ((unsigned)hh < (unsigned)H_) {
            const float* src = x + (((size_t)(b * C_ + c0 + c)) * H_ + hh) * W_ + w0 + q * 4;
            asm volatile("cp.async.cg.shared.global [%0], [%1], 16;"
                         :: "r"(smem_u32(dst)), "l"(src));
        } else {
            *reinterpret_cast<float4*>(dst) = make_float4(0.f, 0.f, 0.f, 0.f);
        }
    }
    // halo columns: 16 ch x 4 rows x 2 sides = 128 scalars
    if (t < 128) {
        int c    = t >> 3;
        int rem  = t & 7;
        int r    = rem >> 1;
        int side = rem & 1;
        int hh   = h0 + r - 1;
        int ww   = side ? (w0 + 32) : (w0 - 1);
        int col  = side ? 36 : 3;
        float* dst = xf + c * XS_CH + r * XS_ROW + col;
        if ((unsigned)hh < (unsigned)H_ && (unsigned)ww < (unsigned)W_) {
            const float* src = x + (((size_t)(b * C_ + c0 + c)) * H_ + hh) * W_ + ww;
            asm volatile("cp.async.ca.shared.global [%0], [%1], 4;"
                         :: "r"(smem_u32(dst)), "l"(src));
        } else {
            *dst = 0.f;
        }
    }
}

// depthwise for chunk cj: 4 pixels of one output row per thread
__device__ __forceinline__ void dw_chunk(float* smem, int cj, int kch, int row,
                                         int pxg, int wb, int a_lo_sel,
                                         uint32_t psel) {
    const float* dk   = smem + DK_F;
    const float* dkc  = dk + (cj * 16 + kch) * 9;
    // output row h0+row uses staged rows row..row+2; taps for px j at fl 3+j..5+j
    const float* rowb = smem + XS_F + (cj & 1) * XS_FLTS + kch * XS_CH
                      + row * XS_ROW + pxg * 4;
    float sv[4];
#pragma unroll
    for (int j = 0; j < 4; j++) sv[j] = 0.f;
#pragma unroll
    for (int r = 0; r < 3; r++) {
        const float* rp = rowb + r * XS_ROW;
        float4 q0 = *reinterpret_cast<const float4*>(rp);
        float4 q1 = *reinterpret_cast<const float4*>(rp + 4);
        float s8  = rp[8];
        float v[9] = {q0.x, q0.y, q0.z, q0.w, q1.x, q1.y, q1.z, q1.w, s8};
        float k0 = dkc[r * 3 + 0], k1 = dkc[r * 3 + 1], k2 = dkc[r * 3 + 2];
#pragma unroll
        for (int j = 0; j < 4; j++) {
            sv[j] = fmaf(k0, v[j + 3], sv[j]);
            sv[j] = fmaf(k1, v[j + 4], sv[j]);
            sv[j] = fmaf(k2, v[j + 5], sv[j]);
        }
    }
    float* abase = smem + AS_F + (cj & 1) * AS_STRIDE + a_lo_sel;
#pragma unroll
    for (int j = 0; j < 4; j++) {
        uint32_t own = split_f16_pair(sv[j]);
        uint32_t partner = __shfl_xor_sync(0xffffffffu, own, 1);
        abase[wb + j * 16] = __uint_as_float(__byte_perm(own, partner, psel));
    }
}

__global__ __launch_bounds__(256, 3)
void fused_kernel(const float* __restrict__ x,
                  const float* __restrict__ pw_b,
                  float* __restrict__ out) {
    extern __shared__ float smem[];
    float* dk = smem + DK_F;

    const int t    = threadIdx.x;
    const int wid  = t >> 5;
    const int lane = t & 31;
    const int w0   = blockIdx.x * 32;
    const int h0   = blockIdx.y * 2;
    const int bb   = blockIdx.z;

    // dw mapping: channel kch; mg: row = mg>>3, pxg = mg&7 (4 px each)
    const int kch = t & 15;
    const int mg  = t >> 4;                   // 0..15
    const int row = mg >> 3;
    const int pxg = mg & 7;
    // A-frag word index for m = row*32 + pxg*4 + j, k = kch (j adds j*16):
    //   mt = row*2 + (pxg>>2); g16 = (pxg&1)*64; mhigh = (pxg>>1)&1
    const int wb = (row * 2 + (pxg >> 2)) * 128 + (pxg & 1) * 64
                 + ((kch >> 1) & 3) * 4 + (kch >> 3) * 2 + ((pxg >> 1) & 1);
    const int a_lo_sel = (kch & 1) ? AS_LO_D : 0;
    const uint32_t psel = (kch & 1) ? 0x3276u : 0x5410u;

    // GEMM warp tiling: 2 m-warps x 4 n-warps, warp tile m32 x n32
    const int wm = wid & 1;
    const int wn = wid >> 1;
    const uint2* bsrc = g_pwf16 + (wn * 4) * 32 + lane;

    // prologue
    stage_xs(x, bb, 0, h0, w0, smem + XS_F, t);
    asm volatile("cp.async.commit_group;" ::: "memory");
    for (int i = t; i < C_ * 9; i += 256)
        dk[i] = g_dynk[bb * C_ * 9 + i];

    float acc[2][4][4];
#pragma unroll
    for (int i = 0; i < 2; i++)
#pragma unroll
        for (int j = 0; j < 4; j++)
#pragma unroll
            for (int k = 0; k < 4; k++) acc[i][j][k] = 0.f;

    asm volatile("cp.async.wait_group 0;" ::: "memory");
    __syncthreads();
    stage_xs(x, bb, 16, h0, w0, smem + XS_F + XS_FLTS, t);
    asm volatile("cp.async.commit_group;" ::: "memory");

    dw_chunk(smem, 0, kch, row, pxg, wb, a_lo_sel, psel);

#pragma unroll 1
    for (int ci = 0; ci < 8; ci++) {
        if (ci < 7)
            asm volatile("cp.async.wait_group 0;" ::: "memory");
        __syncthreads();   // dw(ci) visible; GEMM(ci-1) done with As[(ci+1)&1]

        // B fragments for GEMM(ci): direct LDG, latency covered by dw below
        uint2 bfrag[4];
#pragma unroll
        for (int ntl = 0; ntl < 4; ntl++)
            bfrag[ntl] = __ldg(bsrc + ci * 512 + ntl * 32);

        if (ci < 6) {
            stage_xs(x, bb, (ci + 2) * 16, h0, w0, smem + XS_F + (ci & 1) * XS_FLTS, t);
            asm volatile("cp.async.commit_group;" ::: "memory");
        }

        // dw(ci+1) overlaps GEMM(ci) across warps
        if (ci < 7)
            dw_chunk(smem, ci + 1, kch, row, pxg, wb, a_lo_sel, psel);

        // --- GEMM(ci): one k16 step, 2-term fp16 split ---
        {
            const float* asb = smem + AS_F + (ci & 1) * AS_STRIDE;
            uint4 ah[2], al[2];
#pragma unroll
            for (int mA = 0; mA < 2; mA++) {
                int fi = ((wm * 2 + mA) * 32 + lane) * 4;
                ah[mA] = *reinterpret_cast<const uint4*>(asb + fi);
                al[mA] = *reinterpret_cast<const uint4*>(asb + AS_LO_D + fi);
            }
#pragma unroll
            for (int ntl = 0; ntl < 4; ntl++) {
                uint2 bv = bfrag[ntl];
#pragma unroll
                for (int mA = 0; mA < 2; mA++) {
                    float* a4 = acc[mA][ntl];
                    mma_f16(a4, reinterpret_cast<uint32_t*>(&ah[mA]), bv.x, bv.y);
                    mma_f16(a4, reinterpret_cast<uint32_t*>(&al[mA]), bv.x, bv.y);
                }
            }
        }
    }

    // --- epilogue: D fragment scatter + bias ---
    // mt = wm*2 + mA: output row = h0 + (mt>>1), px base = (mt&1)*16
    const int g   = lane >> 2;
    const int tig = lane & 3;
#pragma unroll
    for (int mA = 0; mA < 2; mA++) {
        int mt = wm * 2 + mA;
        int h  = h0 + (mt >> 1);
        int wp = w0 + (mt & 1) * 16;
#pragma unroll
        for (int ntl = 0; ntl < 4; ntl++) {
            int o = (wn * 4 + ntl) * 8 + 2 * tig;
            float b0v = __ldg(pw_b + o);
            float b1v = __ldg(pw_b + o + 1);
            size_t r0 = (((size_t)(bb * OC_ + o)) * H_ + h) * W_ + wp;
            size_t r1 = r0 + (size_t)H_ * W_;
            const float* a4 = acc[mA][ntl];
            out[r0 + g]     = a4[0] + b0v;
            out[r1 + g]     = a4[1] + b1v;
            out[r0 + g + 8] = a4[2] + b0v;
            out[r1 + g + 8] = a4[3] + b1v;
        }
    }
}

// ---------------------------------------------------------------------------
extern "C" void kernel_launch(void* const* d_in, const int* in_sizes, int n_in,
                              void* d_out, int out_size) {
    const float* x           = (const float*)d_in[0];
    const float* kernel_bank = (const float*)d_in[1];
    const float* attn_w      = (const float*)d_in[2];
    const float* attn_b      = (const float*)d_in[3];
    const float* pw_w        = (const float*)d_in[4];
    const float* pw_b        = (const float*)d_in[5];
    float* out               = (float*)d_out;

    static int smem_set = 0;
    if (!smem_set) {
        cudaFuncSetAttribute(fused_kernel,
                             cudaFuncAttributeMaxDynamicSharedMemorySize,
                             SMEM_FLOATS * 4);
        smem_set = 1;
    }

    pool_kernel<<<B_ * C_, 256>>>(x);
    attn_kernel<<<B_, 128>>>(kernel_bank, attn_w, attn_b);
    split_pw_fp16<<<16, 256>>>(pw_w);
    fused_kernel<<<dim3(W_ / 32, H_ / 2, B_), 256, SMEM_FLOATS * 4>>>(x, pw_b, out);
}

// round 13
// speedup vs baseline: 1.4375x; 1.0625x over previous
#include <cuda_runtime.h>
#include <cuda_fp16.h>
#include <cstdint>

// Problem constants
#define B_  8
#define C_  128
#define H_  256
#define W_  256
#define KB_ 4
#define OC_ 128

// Scratch (static device arrays; no allocation)
__device__ float g_pooled[B_ * C_];
__device__ float g_dynk[B_ * C_ * 9];
// pw_w rounded to fp16, packed in m16n8k16 B-fragment order:
// [ci(8)][nt(16)][lane(32)] x uint2 {b0, b1}
__device__ uint2 g_pwf16[8 * 16 * 32];

// ---------------------------------------------------------------------------
// helpers
// ---------------------------------------------------------------------------
__device__ __forceinline__ uint32_t smem_u32(const void* p) {
    uint32_t a;
    asm("{ .reg .u64 t; cvta.to.shared.u64 t, %1; cvt.u32.u64 %0, t; }"
        : "=r"(a) : "l"(p));
    return a;
}
__device__ __forceinline__ void mma_f16(float* d, const uint32_t* a,
                                        uint32_t b0, uint32_t b1) {
    asm volatile(
        "mma.sync.aligned.m16n8k16.row.col.f32.f16.f16.f32 "
        "{%0,%1,%2,%3}, {%4,%5,%6,%7}, {%8,%9}, {%0,%1,%2,%3};"
        : "+f"(d[0]), "+f"(d[1]), "+f"(d[2]), "+f"(d[3])
        : "r"(a[0]), "r"(a[1]), "r"(a[2]), "r"(a[3]), "r"(b0), "r"(b1));
}

// ---------------------------------------------------------------------------
// Kernel 1: global average pool
// ---------------------------------------------------------------------------
__global__ void pool_kernel(const float* __restrict__ x) {
    const int plane = blockIdx.x;
    const int t = threadIdx.x;
    const float4* p = reinterpret_cast<const float4*>(x + (size_t)plane * (H_ * W_));
    float s = 0.f;
#pragma unroll 8
    for (int it = 0; it < 64; it++) {
        float4 v = p[it * 256 + t];
        s += (v.x + v.y) + (v.z + v.w);
    }
    __shared__ float red[256];
    red[t] = s;
    __syncthreads();
    for (int st = 128; st > 0; st >>= 1) {
        if (t < st) red[t] += red[t + st];
        __syncthreads();
    }
    if (t == 0) g_pooled[plane] = red[0] * (1.f / (H_ * W_));
}

// ---------------------------------------------------------------------------
// Kernel 2: attention -> softmax -> dynamic depthwise kernel per (b,c)
// ---------------------------------------------------------------------------
__global__ void attn_kernel(const float* __restrict__ kernel_bank,
                            const float* __restrict__ attn_w,
                            const float* __restrict__ attn_b) {
    const int b = blockIdx.x;
    const int c = threadIdx.x;               // 128 threads
    __shared__ float red[128];
    __shared__ float logit[KB_];
    __shared__ float attn[KB_];

    float p = g_pooled[b * C_ + c];
    for (int k = 0; k < KB_; k++) {
        red[c] = p * attn_w[k * C_ + c];
        __syncthreads();
        for (int st = 64; st > 0; st >>= 1) {
            if (c < st) red[c] += red[c + st];
            __syncthreads();
        }
        if (c == 0) logit[k] = red[0] + attn_b[k];
        __syncthreads();
    }
    if (c == 0) {
        float mx = logit[0];
        for (int k = 1; k < KB_; k++) mx = fmaxf(mx, logit[k]);
        float s = 0.f;
        for (int k = 0; k < KB_; k++) { attn[k] = expf(logit[k] - mx); s += attn[k]; }
        float inv = 1.f / s;
        for (int k = 0; k < KB_; k++) attn[k] *= inv;
    }
    __syncthreads();
    float a0 = attn[0], a1 = attn[1], a2 = attn[2], a3 = attn[3];
#pragma unroll
    for (int ij = 0; ij < 9; ij++) {
        float s = a0 * kernel_bank[(0 * C_ + c) * 9 + ij]
                + a1 * kernel_bank[(1 * C_ + c) * 9 + ij]
                + a2 * kernel_bank[(2 * C_ + c) * 9 + ij]
                + a3 * kernel_bank[(3 * C_ + c) * 9 + ij];
        g_dynk[(b * C_ + c) * 9 + ij] = s;
    }
}

// ---------------------------------------------------------------------------
// Kernel 2b: round pw_w to fp16, packed in B-fragment order.
// ---------------------------------------------------------------------------
__global__ void split_pw_fp16(const float* __restrict__ pw_w) {
    int idx = blockIdx.x * 256 + threadIdx.x;   // (ci, nt, lane)
    if (idx >= 4096) return;
    int lane = idx & 31;
    int nt   = (idx >> 5) & 15;
    int ci   = idx >> 9;
    int g = lane >> 2, tig = lane & 3;
    int o  = nt * 8 + g;
    int k0 = ci * 16 + 2 * tig;

    uint32_t b0 = (uint32_t)__half_as_ushort(__float2half_rn(pw_w[o * C_ + k0]))
                | ((uint32_t)__half_as_ushort(__float2half_rn(pw_w[o * C_ + k0 + 1])) << 16);
    uint32_t b1 = (uint32_t)__half_as_ushort(__float2half_rn(pw_w[o * C_ + k0 + 8]))
                | ((uint32_t)__half_as_ushort(__float2half_rn(pw_w[o * C_ + k0 + 9])) << 16);
    g_pwf16[idx] = make_uint2(b0, b1);
}

// ---------------------------------------------------------------------------
// Fused dw 3x3 + mma.sync fp16 GEMM (single-fp16 A, fp16 B).
// Grid (W/32=8, H/2=128, B=8), 256 threads, 3 CTAs/SM.
// CTA tile: M=64 = 32 px x 2 output rows, N=128 ocs.
// dw: thread (kch = t&15, mg = t>>4): row = mg>>3, pxg = mg&7 -> 4 px;
//     loads 2x LDS.128 + 1x LDS.32 per staged row. Even kch threads store
//     the packed {k, k+1} fp16x2 word (shfl pairing); one A array only.
// GEMM: 8 warps, 2 m-warps x 4 n-warps; ONE k16 MMA per (mt, nt) per chunk.
// Smem (floats):
//   As[2] : 512 words + 16 pad each (stride 528)
//   xs[2] : 16 ch x 4 rows x 40, ch stride 164 fl (41 16B-units, odd -> CF)
//   dk    : 1152
// Total 7456 floats = 29824 B.
// ---------------------------------------------------------------------------
#define XS_ROW   40
#define XS_CH    164
#define XS_FLTS  (16 * XS_CH)               // 2624 per buffer
#define AS_F     0
#define AS_STRIDE 528
#define XS_F     (2 * AS_STRIDE)            // 1056
#define DK_F     (XS_F + 2 * XS_FLTS)       // 6304
#define SMEM_FLOATS (DK_F + 1152)           // 7456 -> 29824 B

__device__ __forceinline__ void stage_xs(const float* __restrict__ x,
                                         int b, int c0, int h0, int w0,
                                         float* xf, int t) {
    // interior: 16 ch x 4 rows x 8 float4 = 512 f4, 2 per thread
#pragma unroll
    for (int i = 0; i < 2; i++) {
        int idx = t + i * 256;
        int c   = idx >> 5;
        int rem = idx & 31;
        int r   = rem >> 3;
        int q   = rem & 7;
        int hh  = h0 + r - 1;
        float* dst = xf + c * XS_CH + r * XS_ROW + 4 + q * 4;
        if ((unsigned)hh < (unsigned)H_) {
            const float* src = x + (((size_t)(b * C_ + c0 + c)) * H_ + hh) * W_ + w0 + q * 4;
            asm volatile("cp.async.cg.shared.global [%0], [%1], 16;"
                         :: "r"(smem_u32(dst)), "l"(src));
        } else {
            *reinterpret_cast<float4*>(dst) = make_float4(0.f, 0.f, 0.f, 0.f);
        }
    }
    // halo columns: 16 ch x 4 rows x 2 sides = 128 scalars
    if (t < 128) {
        int c    = t >> 3;
        int rem  = t & 7;
        int r    = rem >> 1;
        int side = rem & 1;
        int hh   = h0 + r - 1;
        int ww   = side ? (w0 + 32) : (w0 - 1);
        int col  = side ? 36 : 3;
        float* dst = xf + c * XS_CH + r * XS_ROW + col;
        if ((unsigned)hh < (unsigned)H_ && (unsigned)ww < (unsigned)W_) {
            const float* src = x + (((size_t)(b * C_ + c0 + c)) * H_ + hh) * W_ + ww;
            asm volatile("cp.async.ca.shared.global [%0], [%1], 4;"
                         :: "r"(smem_u32(dst)), "l"(src));
        } else {
            *dst = 0.f;
        }
    }
}

// depthwise for chunk cj: 4 pixels of one output row per thread
__device__ __forceinline__ void dw_chunk(float* smem, int cj, int kch, int row,
                                         int pxg, int wb, bool store) {
    const float* dk   = smem + DK_F;
    const float* dkc  = dk + (cj * 16 + kch) * 9;
    const float* rowb = smem + XS_F + (cj & 1) * XS_FLTS + kch * XS_CH
                      + row * XS_ROW + pxg * 4;
    float sv[4];
#pragma unroll
    for (int j = 0; j < 4; j++) sv[j] = 0.f;
#pragma unroll
    for (int r = 0; r < 3; r++) {
        const float* rp = rowb + r * XS_ROW;
        float4 q0 = *reinterpret_cast<const float4*>(rp);
        float4 q1 = *reinterpret_cast<const float4*>(rp + 4);
        float s8  = rp[8];
        float v[9] = {q0.x, q0.y, q0.z, q0.w, q1.x, q1.y, q1.z, q1.w, s8};
        float k0 = dkc[r * 3 + 0], k1 = dkc[r * 3 + 1], k2 = dkc[r * 3 + 2];
#pragma unroll
        for (int j = 0; j < 4; j++) {
            sv[j] = fmaf(k0, v[j + 3], sv[j]);
            sv[j] = fmaf(k1, v[j + 4], sv[j]);
            sv[j] = fmaf(k2, v[j + 5], sv[j]);
        }
    }
    float* abase = smem + AS_F + (cj & 1) * AS_STRIDE;
#pragma unroll
    for (int j = 0; j < 4; j++) {
        uint32_t own = (uint32_t)__half_as_ushort(__float2half_rn(sv[j]));
        uint32_t partner = __shfl_xor_sync(0xffffffffu, own, 1);
        if (store)
            abase[wb + j * 16] =
                __uint_as_float(__byte_perm(own, partner, 0x5410));
    }
}

__global__ __launch_bounds__(256, 3)
void fused_kernel(const float* __restrict__ x,
                  const float* __restrict__ pw_b,
                  float* __restrict__ out) {
    extern __shared__ float smem[];
    float* dk = smem + DK_F;

    const int t    = threadIdx.x;
    const int wid  = t >> 5;
    const int lane = t & 31;
    const int w0   = blockIdx.x * 32;
    const int h0   = blockIdx.y * 2;
    const int bb   = blockIdx.z;

    // dw mapping: channel kch; mg: row = mg>>3, pxg = mg&7 (4 px each)
    const int kch = t & 15;
    const int mg  = t >> 4;                   // 0..15
    const int row = mg >> 3;
    const int pxg = mg & 7;
    // A-frag word index for m = row*32 + pxg*4 + j, k-pair e = kch>>1:
    //   mt = row*2 + (pxg>>2); word-in-frag lane' = j'*4 + (e&3), reg = (e>>2)*2 + mhigh
    const int wb = (row * 2 + (pxg >> 2)) * 128 + (pxg & 1) * 64
                 + ((kch >> 1) & 3) * 4 + (kch >> 3) * 2 + ((pxg >> 1) & 1);
    const bool a_store = (kch & 1) == 0;

    // GEMM warp tiling: 2 m-warps x 4 n-warps, warp tile m32 x n32
    const int wm = wid & 1;
    const int wn = wid >> 1;
    const uint2* bsrc = g_pwf16 + (wn * 4) * 32 + lane;

    // prologue
    stage_xs(x, bb, 0, h0, w0, smem + XS_F, t);
    asm volatile("cp.async.commit_group;" ::: "memory");
    for (int i = t; i < C_ * 9; i += 256)
        dk[i] = g_dynk[bb * C_ * 9 + i];

    float acc[2][4][4];
#pragma unroll
    for (int i = 0; i < 2; i++)
#pragma unroll
        for (int j = 0; j < 4; j++)
#pragma unroll
            for (int k = 0; k < 4; k++) acc[i][j][k] = 0.f;

    asm volatile("cp.async.wait_group 0;" ::: "memory");
    __syncthreads();
    stage_xs(x, bb, 16, h0, w0, smem + XS_F + XS_FLTS, t);
    asm volatile("cp.async.commit_group;" ::: "memory");

    dw_chunk(smem, 0, kch, row, pxg, wb, a_store);

#pragma unroll 1
    for (int ci = 0; ci < 8; ci++) {
        if (ci < 7)
            asm volatile("cp.async.wait_group 0;" ::: "memory");
        __syncthreads();   // dw(ci) visible; GEMM(ci-1) done with As[(ci+1)&1]

        // B fragments for GEMM(ci): direct LDG, latency covered by dw below
        uint2 bfrag[4];
#pragma unroll
        for (int ntl = 0; ntl < 4; ntl++)
            bfrag[ntl] = __ldg(bsrc + ci * 512 + ntl * 32);

        if (ci < 6) {
            stage_xs(x, bb, (ci + 2) * 16, h0, w0, smem + XS_F + (ci & 1) * XS_FLTS, t);
            asm volatile("cp.async.commit_group;" ::: "memory");
        }

        // dw(ci+1) overlaps GEMM(ci) across warps
        if (ci < 7)
            dw_chunk(smem, ci + 1, kch, row, pxg, wb, a_store);

        // --- GEMM(ci): one k16 MMA per (mt, nt) ---
        {
            const float* asb = smem + AS_F + (ci & 1) * AS_STRIDE;
            uint4 ah[2];
#pragma unroll
            for (int mA = 0; mA < 2; mA++) {
                int fi = ((wm * 2 + mA) * 32 + lane) * 4;
                ah[mA] = *reinterpret_cast<const uint4*>(asb + fi);
            }
#pragma unroll
            for (int ntl = 0; ntl < 4; ntl++) {
                uint2 bv = bfrag[ntl];
#pragma unroll
                for (int mA = 0; mA < 2; mA++)
                    mma_f16(acc[mA][ntl], reinterpret_cast<uint32_t*>(&ah[mA]),
                            bv.x, bv.y);
            }
        }
    }

    // --- epilogue: D fragment scatter + bias ---
    // mt = wm*2 + mA: output row = h0 + (mt>>1), px base = (mt&1)*16
    const int g   = lane >> 2;
    const int tig = lane & 3;
#pragma unroll
    for (int mA = 0; mA < 2; mA++) {
        int mt = wm * 2 + mA;
        int h  = h0 + (mt >> 1);
        int wp = w0 + (mt & 1) * 16;
#pragma unroll
        for (int ntl = 0; ntl < 4; ntl++) {
            int o = (wn * 4 + ntl) * 8 + 2 * tig;
            float b0v = __ldg(pw_b + o);
            float b1v = __ldg(pw_b + o + 1);
            size_t r0 = (((size_t)(bb * OC_ + o)) * H_ + h) * W_ + wp;
            size_t r1 = r0 + (size_t)H_ * W_;
            const float* a4 = acc[mA][ntl];
            out[r0 + g]     = a4[0] + b0v;
            out[r1 + g]     = a4[1] + b1v;
            out[r0 + g + 8] = a4[2] + b0v;
            out[r1 + g + 8] = a4[3] + b1v;
        }
    }
}

// ---------------------------------------------------------------------------
extern "C" void kernel_launch(void* const* d_in, const int* in_sizes, int n_in,
                              void* d_out, int out_size) {
    const float* x           = (const float*)d_in[0];
    const float* kernel_bank = (const float*)d_in[1];
    const float* attn_w      = (const float*)d_in[2];
    const float* attn_b      = (const float*)d_in[3];
    const float* pw_w        = (const float*)d_in[4];
    const float* pw_b        = (const float*)d_in[5];
    float* out               = (float*)d_out;

    static int smem_set = 0;
    if (!smem_set) {
        cudaFuncSetAttribute(fused_kernel,
                             cudaFuncAttributeMaxDynamicSharedMemorySize,
                             SMEM_FLOATS * 4);
        smem_set = 1;
    }

    pool_kernel<<<B_ * C_, 256>>>(x);
    attn_kernel<<<B_, 128>>>(kernel_bank, attn_w, attn_b);
    split_pw_fp16<<<16, 256>>>(pw_w);
    fused_kernel<<<dim3(W_ / 32, H_ / 2, B_), 256, SMEM_FLOATS * 4>>>(x, pw_b, out);
}

// round 14
// speedup vs baseline: 1.5041x; 1.0463x over previous
#include <cuda_runtime.h>
#include <cuda_fp16.h>
#include <cstdint>

// Problem constants
#define B_  8
#define C_  128
#define H_  256
#define W_  256
#define KB_ 4
#define OC_ 128

// Scratch (static device arrays; no allocation)
__device__ float g_pooled[B_ * C_];
__device__ float g_dynk[B_ * C_ * 9];
// pw_w rounded to fp16, packed in m16n8k16 B-fragment order:
// [ci(8)][nt(16)][lane(32)] x uint2 {b0, b1}
__device__ uint2 g_pwf16[8 * 16 * 32];

// ---------------------------------------------------------------------------
// helpers
// ---------------------------------------------------------------------------
__device__ __forceinline__ uint32_t smem_u32(const void* p) {
    uint32_t a;
    asm("{ .reg .u64 t; cvta.to.shared.u64 t, %1; cvt.u32.u64 %0, t; }"
        : "=r"(a) : "l"(p));
    return a;
}
__device__ __forceinline__ void mma_f16(float* d, const uint32_t* a,
                                        uint32_t b0, uint32_t b1) {
    asm volatile(
        "mma.sync.aligned.m16n8k16.row.col.f32.f16.f16.f32 "
        "{%0,%1,%2,%3}, {%4,%5,%6,%7}, {%8,%9}, {%0,%1,%2,%3};"
        : "+f"(d[0]), "+f"(d[1]), "+f"(d[2]), "+f"(d[3])
        : "r"(a[0]), "r"(a[1]), "r"(a[2]), "r"(a[3]), "r"(b0), "r"(b1));
}

// ---------------------------------------------------------------------------
// Kernel 1: global average pool
// ---------------------------------------------------------------------------
__global__ void pool_kernel(const float* __restrict__ x) {
    const int plane = blockIdx.x;
    const int t = threadIdx.x;
    const float4* p = reinterpret_cast<const float4*>(x + (size_t)plane * (H_ * W_));
    float s = 0.f;
#pragma unroll 8
    for (int it = 0; it < 64; it++) {
        float4 v = p[it * 256 + t];
        s += (v.x + v.y) + (v.z + v.w);
    }
    __shared__ float red[256];
    red[t] = s;
    __syncthreads();
    for (int st = 128; st > 0; st >>= 1) {
        if (t < st) red[t] += red[t + st];
        __syncthreads();
    }
    if (t == 0) g_pooled[plane] = red[0] * (1.f / (H_ * W_));
}

// ---------------------------------------------------------------------------
// Kernel 2: attention -> softmax -> dynamic depthwise kernel per (b,c)
// ---------------------------------------------------------------------------
__global__ void attn_kernel(const float* __restrict__ kernel_bank,
                            const float* __restrict__ attn_w,
                            const float* __restrict__ attn_b) {
    const int b = blockIdx.x;
    const int c = threadIdx.x;               // 128 threads
    __shared__ float red[128];
    __shared__ float logit[KB_];
    __shared__ float attn[KB_];

    float p = g_pooled[b * C_ + c];
    for (int k = 0; k < KB_; k++) {
        red[c] = p * attn_w[k * C_ + c];
        __syncthreads();
        for (int st = 64; st > 0; st >>= 1) {
            if (c < st) red[c] += red[c + st];
            __syncthreads();
        }
        if (c == 0) logit[k] = red[0] + attn_b[k];
        __syncthreads();
    }
    if (c == 0) {
        float mx = logit[0];
        for (int k = 1; k < KB_; k++) mx = fmaxf(mx, logit[k]);
        float s = 0.f;
        for (int k = 0; k < KB_; k++) { attn[k] = expf(logit[k] - mx); s += attn[k]; }
        float inv = 1.f / s;
        for (int k = 0; k < KB_; k++) attn[k] *= inv;
    }
    __syncthreads();
    float a0 = attn[0], a1 = attn[1], a2 = attn[2], a3 = attn[3];
#pragma unroll
    for (int ij = 0; ij < 9; ij++) {
        float s = a0 * kernel_bank[(0 * C_ + c) * 9 + ij]
                + a1 * kernel_bank[(1 * C_ + c) * 9 + ij]
                + a2 * kernel_bank[(2 * C_ + c) * 9 + ij]
                + a3 * kernel_bank[(3 * C_ + c) * 9 + ij];
        g_dynk[(b * C_ + c) * 9 + ij] = s;
    }
}

// ---------------------------------------------------------------------------
// Kernel 2b: round pw_w to fp16, packed in B-fragment order.
// ---------------------------------------------------------------------------
__global__ void split_pw_fp16(const float* __restrict__ pw_w) {
    int idx = blockIdx.x * 256 + threadIdx.x;   // (ci, nt, lane)
    if (idx >= 4096) return;
    int lane = idx & 31;
    int nt   = (idx >> 5) & 15;
    int ci   = idx >> 9;
    int g = lane >> 2, tig = lane & 3;
    int o  = nt * 8 + g;
    int k0 = ci * 16 + 2 * tig;

    uint32_t b0 = (uint32_t)__half_as_ushort(__float2half_rn(pw_w[o * C_ + k0]))
                | ((uint32_t)__half_as_ushort(__float2half_rn(pw_w[o * C_ + k0 + 1])) << 16);
    uint32_t b1 = (uint32_t)__half_as_ushort(__float2half_rn(pw_w[o * C_ + k0 + 8]))
                | ((uint32_t)__half_as_ushort(__float2half_rn(pw_w[o * C_ + k0 + 9])) << 16);
    g_pwf16[idx] = make_uint2(b0, b1);
}

// ---------------------------------------------------------------------------
// Fused dw 3x3 + mma.sync fp16 GEMM (single-fp16 A, fp16 B).
// Grid (W/32=8, H/2=128, B=8), 256 threads, 3 CTAs/SM.
// CTA tile: M=64 = 32 px x 2 output rows, N=128 ocs.
// dw on warps 0-3 (128 threads): thread (kch = t&15, pxg = (t>>4)&7)
//   computes 4 px x BOTH output rows from 4 staged rows (row reuse:
//   4x(2 LDS.128 + LDS.32) for 8 outputs).
// GEMM: 8 warps, 2 m-warps x 4 n-warps; ONE k16 MMA per (mt, nt) per chunk.
// Smem (floats):
//   As[2] : 512 words + 16 pad each (stride 528)
//   xs[2] : 16 ch x 4 rows x 40, ch stride 164 fl (41 16B-units, odd -> CF)
//   dk    : 1152
// Total 7456 floats = 29824 B.
// ---------------------------------------------------------------------------
#define XS_ROW   40
#define XS_CH    164
#define XS_FLTS  (16 * XS_CH)               // 2624 per buffer
#define AS_F     0
#define AS_STRIDE 528
#define XS_F     (2 * AS_STRIDE)            // 1056
#define DK_F     (XS_F + 2 * XS_FLTS)       // 6304
#define SMEM_FLOATS (DK_F + 1152)           // 7456 -> 29824 B

__device__ __forceinline__ void stage_xs(const float* __restrict__ x,
                                         int b, int c0, int h0, int w0,
                                         float* xf, int t) {
    // interior: 16 ch x 4 rows x 8 float4 = 512 f4, 2 per thread
#pragma unroll
    for (int i = 0; i < 2; i++) {
        int idx = t + i * 256;
        int c   = idx >> 5;
        int rem = idx & 31;
        int r   = rem >> 3;
        int q   = rem & 7;
        int hh  = h0 + r - 1;
        float* dst = xf + c * XS_CH + r * XS_ROW + 4 + q * 4;
        if ((unsigned)hh < (unsigned)H_) {
            const float* src = x + (((size_t)(b * C_ + c0 + c)) * H_ + hh) * W_ + w0 + q * 4;
            asm volatile("cp.async.cg.shared.global [%0], [%1], 16;"
                         :: "r"(smem_u32(dst)), "l"(src));
        } else {
            *reinterpret_cast<float4*>(dst) = make_float4(0.f, 0.f, 0.f, 0.f);
        }
    }
    // halo columns: 16 ch x 4 rows x 2 sides = 128 scalars
    if (t < 128) {
        int c    = t >> 3;
        int rem  = t & 7;
        int r    = rem >> 1;
        int side = rem & 1;
        int hh   = h0 + r - 1;
        int ww   = side ? (w0 + 32) : (w0 - 1);
        int col  = side ? 36 : 3;
        float* dst = xf + c * XS_CH + r * XS_ROW + col;
        if ((unsigned)hh < (unsigned)H_ && (unsigned)ww < (unsigned)W_) {
            const float* src = x + (((size_t)(b * C_ + c0 + c)) * H_ + hh) * W_ + ww;
            asm volatile("cp.async.ca.shared.global [%0], [%1], 4;"
                         :: "r"(smem_u32(dst)), "l"(src));
        } else {
            *dst = 0.f;
        }
    }
}

// depthwise for chunk cj: 4 pixels x 2 output rows per thread (row reuse)
__device__ __forceinline__ void dw_chunk2(float* smem, int cj, int kch, int pxg,
                                          int wb0, bool store) {
    const float* dk   = smem + DK_F;
    const float* dkc  = dk + (cj * 16 + kch) * 9;
    const float* rowb = smem + XS_F + (cj & 1) * XS_FLTS + kch * XS_CH + pxg * 4;
    float s0[4], s1[4];
#pragma unroll
    for (int j = 0; j < 4; j++) { s0[j] = 0.f; s1[j] = 0.f; }
#pragma unroll
    for (int r = 0; r < 4; r++) {
        const float* rp = rowb + r * XS_ROW;
        float4 q0 = *reinterpret_cast<const float4*>(rp);
        float4 q1 = *reinterpret_cast<const float4*>(rp + 4);
        float s8  = rp[8];
        float v[9] = {q0.x, q0.y, q0.z, q0.w, q1.x, q1.y, q1.z, q1.w, s8};
        if (r < 3) {     // output row 0, kernel row r
            float k0 = dkc[r * 3 + 0], k1 = dkc[r * 3 + 1], k2 = dkc[r * 3 + 2];
#pragma unroll
            for (int j = 0; j < 4; j++) {
                s0[j] = fmaf(k0, v[j + 3], s0[j]);
                s0[j] = fmaf(k1, v[j + 4], s0[j]);
                s0[j] = fmaf(k2, v[j + 5], s0[j]);
            }
        }
        if (r > 0) {     // output row 1, kernel row r-1
            float k0 = dkc[(r - 1) * 3 + 0], k1 = dkc[(r - 1) * 3 + 1],
                  k2 = dkc[(r - 1) * 3 + 2];
#pragma unroll
            for (int j = 0; j < 4; j++) {
                s1[j] = fmaf(k0, v[j + 3], s1[j]);
                s1[j] = fmaf(k1, v[j + 4], s1[j]);
                s1[j] = fmaf(k2, v[j + 5], s1[j]);
            }
        }
    }
    float* abase = smem + AS_F + (cj & 1) * AS_STRIDE;
#pragma unroll
    for (int j = 0; j < 4; j++) {
        uint32_t own = (uint32_t)__half_as_ushort(__float2half_rn(s0[j]));
        uint32_t partner = __shfl_xor_sync(0xffffffffu, own, 1);
        if (store)
            abase[wb0 + j * 16] =
                __uint_as_float(__byte_perm(own, partner, 0x5410));
    }
#pragma unroll
    for (int j = 0; j < 4; j++) {
        uint32_t own = (uint32_t)__half_as_ushort(__float2half_rn(s1[j]));
        uint32_t partner = __shfl_xor_sync(0xffffffffu, own, 1);
        if (store)
            abase[wb0 + 256 + j * 16] =       // row 1: mt += 2 -> +256 words
                __uint_as_float(__byte_perm(own, partner, 0x5410));
    }
}

__global__ __launch_bounds__(256, 3)
void fused_kernel(const float* __restrict__ x,
                  const float* __restrict__ pw_b,
                  float* __restrict__ out) {
    extern __shared__ float smem[];
    float* dk = smem + DK_F;

    const int t    = threadIdx.x;
    const int wid  = t >> 5;
    const int lane = t & 31;
    const int w0   = blockIdx.x * 32;
    const int h0   = blockIdx.y * 2;
    const int bb   = blockIdx.z;

    // dw mapping (threads 0-127): channel kch, px group pxg (4 px, both rows)
    const int kch = t & 15;
    const int pxg = (t >> 4) & 7;
    const bool is_dw = (t < 128);
    // A-frag word index for row 0, m = pxg*4 + j, k-pair e = kch>>1:
    const int wb0 = (pxg >> 2) * 128 + (pxg & 1) * 64
                  + ((kch >> 1) & 3) * 4 + (kch >> 3) * 2 + ((pxg >> 1) & 1);
    const bool a_store = is_dw && ((kch & 1) == 0);

    // GEMM warp tiling: 2 m-warps x 4 n-warps, warp tile m32 x n32
    const int wm = wid & 1;
    const int wn = wid >> 1;
    const uint2* bsrc = g_pwf16 + (wn * 4) * 32 + lane;

    // prologue
    stage_xs(x, bb, 0, h0, w0, smem + XS_F, t);
    asm volatile("cp.async.commit_group;" ::: "memory");
    for (int i = t; i < C_ * 9; i += 256)
        dk[i] = g_dynk[bb * C_ * 9 + i];

    float acc[2][4][4];
#pragma unroll
    for (int i = 0; i < 2; i++)
#pragma unroll
        for (int j = 0; j < 4; j++)
#pragma unroll
            for (int k = 0; k < 4; k++) acc[i][j][k] = 0.f;

    asm volatile("cp.async.wait_group 0;" ::: "memory");
    __syncthreads();
    stage_xs(x, bb, 16, h0, w0, smem + XS_F + XS_FLTS, t);
    asm volatile("cp.async.commit_group;" ::: "memory");

    if (is_dw) dw_chunk2(smem, 0, kch, pxg, wb0, a_store);

#pragma unroll 1
    for (int ci = 0; ci < 8; ci++) {
        if (ci < 7)
            asm volatile("cp.async.wait_group 0;" ::: "memory");
        __syncthreads();   // dw(ci) visible; GEMM(ci-1) done with As[(ci+1)&1]

        // B fragments for GEMM(ci): direct LDG, latency covered by dw below
        uint2 bfrag[4];
#pragma unroll
        for (int ntl = 0; ntl < 4; ntl++)
            bfrag[ntl] = __ldg(bsrc + ci * 512 + ntl * 32);

        if (ci < 6) {
            stage_xs(x, bb, (ci + 2) * 16, h0, w0, smem + XS_F + (ci & 1) * XS_FLTS, t);
            asm volatile("cp.async.commit_group;" ::: "memory");
        }

        // dw(ci+1) overlaps GEMM(ci) across warps
        if (ci < 7 && is_dw)
            dw_chunk2(smem, ci + 1, kch, pxg, wb0, a_store);

        // --- GEMM(ci): one k16 MMA per (mt, nt) ---
        {
            const float* asb = smem + AS_F + (ci & 1) * AS_STRIDE;
            uint4 ah[2];
#pragma unroll
            for (int mA = 0; mA < 2; mA++) {
                int fi = ((wm * 2 + mA) * 32 + lane) * 4;
                ah[mA] = *reinterpret_cast<const uint4*>(asb + fi);
            }
#pragma unroll
            for (int ntl = 0; ntl < 4; ntl++) {
                uint2 bv = bfrag[ntl];
#pragma unroll
                for (int mA = 0; mA < 2; mA++)
                    mma_f16(acc[mA][ntl], reinterpret_cast<uint32_t*>(&ah[mA]),
                            bv.x, bv.y);
            }
        }
    }

    // --- epilogue: D fragment scatter + bias ---
    // mt = wm*2 + mA: output row = h0 + (mt>>1), px base = (mt&1)*16
    const int g   = lane >> 2;
    const int tig = lane & 3;
#pragma unroll
    for (int mA = 0; mA < 2; mA++) {
        int mt = wm * 2 + mA;
        int h  = h0 + (mt >> 1);
        int wp = w0 + (mt & 1) * 16;
#pragma unroll
        for (int ntl = 0; ntl < 4; ntl++) {
            int o = (wn * 4 + ntl) * 8 + 2 * tig;
            float b0v = __ldg(pw_b + o);
            float b1v = __ldg(pw_b + o + 1);
            size_t r0 = (((size_t)(bb * OC_ + o)) * H_ + h) * W_ + wp;
            size_t r1 = r0 + (size_t)H_ * W_;
            const float* a4 = acc[mA][ntl];
            out[r0 + g]     = a4[0] + b0v;
            out[r1 + g]     = a4[1] + b1v;
            out[r0 + g + 8] = a4[2] + b0v;
            out[r1 + g + 8] = a4[3] + b1v;
        }
    }
}

// ---------------------------------------------------------------------------
extern "C" void kernel_launch(void* const* d_in, const int* in_sizes, int n_in,
                              void* d_out, int out_size) {
    const float* x           = (const float*)d_in[0];
    const float* kernel_bank = (const float*)d_in[1];
    const float* attn_w      = (const float*)d_in[2];
    const float* attn_b      = (const float*)d_in[3];
    const float* pw_w        = (const float*)d_in[4];
    const float* pw_b        = (const float*)d_in[5];
    float* out               = (float*)d_out;

    static int smem_set = 0;
    if (!smem_set) {
        cudaFuncSetAttribute(fused_kernel,
                             cudaFuncAttributeMaxDynamicSharedMemorySize,
                             SMEM_FLOATS * 4);
        smem_set = 1;
    }

    pool_kernel<<<B_ * C_, 256>>>(x);
    attn_kernel<<<B_, 128>>>(kernel_bank, attn_w, attn_b);
    split_pw_fp16<<<16, 256>>>(pw_w);
    fused_kernel<<<dim3(W_ / 32, H_ / 2, B_), 256, SMEM_FLOATS * 4>>>(x, pw_b, out);
}